// round 14
// baseline (speedup 1.0000x reference)
#include <cuda_runtime.h>
#include <cuda_fp16.h>
#include <cstdint>

// Problem constants
#define BB 2
#define LL 2048
#define DD 768
#define DI 1536
#define DS 16
#define DTR 48
#define KK 4
#define ROWS (BB*LL)            // 4096
#define DBC_W (DTR + 2*DS)      // 80
#define LDXZ (4*DI)             // 6144
#define NC 16                   // scan chunks
#define CL (LL/NC)              // 128 steps per chunk

// ---------------- scratch (device globals; allocation-free) ----------------
__device__ __align__(16) __half g_xz_h [(size_t)ROWS*LDXZ];
__device__ __align__(16) __half g_xn_h [ROWS*DD];
__device__ __align__(16) __half g_xch_f[(size_t)ROWS*DI];
__device__ __align__(16) float  g_dbc_f[(size_t)ROWS*DBC_W];
__device__ __align__(16) __half g_dbch_f[(size_t)ROWS*DBC_W];
__device__ __align__(16) float  g_dt_f [(size_t)ROWS*DI];
__device__ __align__(16) __half g_yh_f [(size_t)ROWS*DI];
__device__ __align__(16) __half g_xch_b[(size_t)ROWS*DI];
__device__ __align__(16) float  g_dbc_b[(size_t)ROWS*DBC_W];
__device__ __align__(16) __half g_dbch_b[(size_t)ROWS*DBC_W];
__device__ __align__(16) float  g_dt_b [(size_t)ROWS*DI];
__device__ __align__(16) __half g_yh_b [(size_t)ROWS*DI];
__device__ __align__(16) float  g_h    [ROWS*DD];
__device__ __align__(16) __half g_hn_h [ROWS*DD];
__device__ __align__(16) __half g_ff1_h[(size_t)ROWS*4*DD];
__device__ __align__(16) float  g_p0   [ROWS*DD];   // split-K partials
__device__ __align__(16) float  g_p1   [ROWS*DD];

// chunked-scan intermediates (per branch)
#define SCAN_ST (BB*DI*NC*DS)   // 786432
__device__ __align__(16) float g_hp_f[SCAN_ST];
__device__ __align__(16) float g_pe_f[SCAN_ST];
__device__ __align__(16) float g_h0_f[SCAN_ST];
__device__ __align__(16) float g_hp_b[SCAN_ST];
__device__ __align__(16) float g_pe_b[SCAN_ST];
__device__ __align__(16) float g_h0_b[SCAN_ST];

// fused out_proj+mix: transposed out weights + combined weights
__device__ __align__(16) __half g_owT  [2*(size_t)DI*DD];     // fowT | bowT
__device__ __align__(16) __half g_wcomb[(size_t)DD*2*DI];     // [768 x 3072]

// fp16 weight scratch
#define W_IN   (2*DI*DD)
#define W_XP   (DBC_W*DI)
#define W_DT   (DI*DTR)
#define W_MIX  (DD*2*DD)
#define W_FF1  (4*DD*DD)
#define W_FF2  (DD*4*DD)
#define OFF_FIN  0
#define OFF_BIN  (OFF_FIN + W_IN)
#define OFF_FXP  (OFF_BIN + W_IN)
#define OFF_BXP  (OFF_FXP + W_XP)
#define OFF_FDT  (OFF_BXP + W_XP)
#define OFF_BDT  (OFF_FDT + W_DT)
#define OFF_MIX  (OFF_BDT + W_DT)
#define OFF_FF1  (OFF_MIX + W_MIX)
#define OFF_FF2  (OFF_FF1 + W_FF1)
#define W_TOTAL  (OFF_FF2 + W_FF2)
__device__ __align__(16) __half g_wh[W_TOTAL];

// ---------------- helpers ----------------
__device__ __forceinline__ float siluf(float x) {
    return x / (1.0f + __expf(-x));
}
__device__ __forceinline__ float geluf(float x) {
    float x3 = x * x * x;
    return 0.5f * x * (1.0f + tanhf(0.7978845608028654f * (x + 0.044715f * x3)));
}
__device__ __forceinline__ float softplusf(float x) {
    if (x > 20.0f) return x;
    return log1pf(__expf(x));
}

__device__ __forceinline__ void cpa16(uint32_t dst, const void* src, bool v) {
    int sz = v ? 16 : 0;
    asm volatile("cp.async.cg.shared.global [%0], [%1], 16, %2;"
        :: "r"(dst), "l"(src), "r"(sz) : "memory");
}
#define CP_COMMIT() asm volatile("cp.async.commit_group;" ::: "memory")
#define CP_WAIT(n)  asm volatile("cp.async.wait_group %0;" :: "n"(n) : "memory")

__device__ __forceinline__ uint32_t smem_u32(const void* p) {
    uint32_t a;
    asm("{ .reg .u64 t; cvta.to.shared.u64 t, %1; cvt.u32.u64 %0, t; }" : "=r"(a) : "l"(p));
    return a;
}
__device__ __forceinline__ void mma_f16(float* d, const uint32_t* a, const uint32_t* b) {
    asm volatile("mma.sync.aligned.m16n8k16.row.col.f32.f16.f16.f32 "
                 "{%0,%1,%2,%3}, {%4,%5,%6,%7}, {%8,%9}, {%0,%1,%2,%3};"
                 : "+f"(d[0]), "+f"(d[1]), "+f"(d[2]), "+f"(d[3])
                 : "r"(a[0]), "r"(a[1]), "r"(a[2]), "r"(a[3]),
                   "r"(b[0]), "r"(b[1]));
}

// ---------------- one-shot weight conversion fp32 -> fp16 ----------------
template<int NS>
struct CvtSegs {
    const float* s[NS];
    __half* d[NS];
    int n[NS];
};
template<int NS>
__global__ void cvt_weights(CvtSegs<NS> sg) {
    int stride = gridDim.x * blockDim.x;
    int i0 = blockIdx.x * blockDim.x + threadIdx.x;
    #pragma unroll
    for (int k = 0; k < NS; k++) {
        const float4* s4 = (const float4*)sg.s[k];
        __half2* d2 = (__half2*)sg.d[k];
        int n4 = sg.n[k] >> 2;
        for (int i = i0; i < n4; i += stride) {
            float4 v = s4[i];
            d2[2*i]   = __floats2half2_rn(v.x, v.y);
            d2[2*i+1] = __floats2half2_rn(v.z, v.w);
        }
    }
}

// ---------------- out_w transpose: fp32 [768x1536] -> fp16 [1536x768] -----
__global__ void transpose_w(const float* __restrict__ s0, const float* __restrict__ s1,
                            __half* __restrict__ dst) {
    __shared__ __half tile[32][33];
    const float* src = blockIdx.z ? s1 : s0;
    __half* d = dst + (size_t)blockIdx.z * DI * DD;
    int kx = blockIdx.x * 32 + threadIdx.x;   // k in [0,1536)
    int jy = blockIdx.y * 32 + threadIdx.y;   // j in [0,768)
    tile[threadIdx.y][threadIdx.x] = __float2half(src[(size_t)jy * DI + kx]);
    __syncthreads();
    int k = blockIdx.x * 32 + threadIdx.y;
    int j = blockIdx.y * 32 + threadIdx.x;
    d[(size_t)k * DD + j] = tile[threadIdx.x][threadIdx.y];
}

// ---------------- split-K reduce: C = p0 + p1 + bias + res ----------------
__global__ void reduce2_kernel(const float* __restrict__ p0,
                               const float* __restrict__ p1,
                               const float* __restrict__ bias,
                               const float* __restrict__ res,
                               float* __restrict__ C) {
    int i = blockIdx.x * blockDim.x + threadIdx.x;   // float4 index
    if (i * 4 >= ROWS * DD) return;
    float4 a = ((const float4*)p0)[i];
    float4 b = ((const float4*)p1)[i];
    float4 r = ((const float4*)res)[i];
    int col = (i * 4) % DD;
    a.x += b.x + bias[col + 0] + r.x;
    a.y += b.y + bias[col + 1] + r.y;
    a.z += b.z + bias[col + 2] + r.z;
    a.w += b.w + bias[col + 3] + r.w;
    ((float4*)C)[i] = a;
}

// ================= fp16 mma.sync GEMM (fp32 accumulate) =================
#define GBM 128
#define GBN 128
#define GBK 64
#define KH 72
#define STAGE_B (GBM*KH*2)
#define SMEM_GEMM (4*STAGE_B)

template<int ACT, bool CAT, bool WF32, bool WH16>
__global__ __launch_bounds__(256, 2)
void hgemm(const __half* __restrict__ A, const __half* __restrict__ A2,
           int ksplit, int lda,
           const __half* __restrict__ W, int ldw,
           float* __restrict__ C, __half* __restrict__ Ch, int ldc,
           int M, int N, int Kd,
           const float* __restrict__ bias,
           const float* __restrict__ res, int ldres) {
    extern __shared__ __half smh[];
    __half* As = smh;
    __half* Bs = smh + 2 * GBM * KH;
    uint32_t sA = smem_u32(As);
    uint32_t sB = smem_u32(Bs);

    int tid = threadIdx.x;
    int lane = tid & 31, wid = tid >> 5;
    int bm = blockIdx.y * GBM, bn = blockIdx.x * GBN;
    int wm = (wid & 1) * 64, wn = (wid >> 1) * 32;
    int g = lane >> 2, l = lane & 3;

    float acc[4][4][4];
    #pragma unroll
    for (int f = 0; f < 4; f++)
        #pragma unroll
        for (int j = 0; j < 4; j++)
            #pragma unroll
            for (int c = 0; c < 4; c++) acc[f][j][c] = 0.f;

    auto load_stage = [&](int buf, int kt) {
        int k0 = kt * GBK;
        const __half* srcA = A;
        int kbase = k0;
        if (CAT && k0 >= ksplit) { srcA = A2; kbase = k0 - ksplit; }
        #pragma unroll
        for (int t = 0; t < 4; t++) {
            int c = tid + t * 256;
            int row = c >> 3, seg = c & 7;
            bool kv = (k0 + seg * 8) < Kd;
            int gm = bm + row;
            bool va = kv && (gm < M);
            cpa16(sA + buf * STAGE_B + row * (KH*2) + seg * 16,
                  srcA + (size_t)(va ? gm : 0) * lda + (va ? (kbase + seg * 8) : 0), va);
            int gn = bn + row;
            bool vb = kv && (gn < N);
            cpa16(sB + buf * STAGE_B + row * (KH*2) + seg * 16,
                  W + (size_t)(vb ? gn : 0) * ldw + (vb ? (k0 + seg * 8) : 0), vb);
        }
        CP_COMMIT();
    };

    const int NT = (Kd + GBK - 1) / GBK;
    load_stage(0, 0);

    for (int kt = 0; kt < NT; kt++) {
        int buf = kt & 1;
        if (kt + 1 < NT) {
            load_stage(buf ^ 1, kt + 1);
            CP_WAIT(1);
        } else {
            CP_WAIT(0);
        }
        __syncthreads();

        const uint32_t* as = (const uint32_t*)(As + buf * GBM * KH);
        const uint32_t* bs = (const uint32_t*)(Bs + buf * GBN * KH);
        #pragma unroll
        for (int s = 0; s < 4; s++) {
            int w0 = s * 8 + l;
            uint32_t af[4][4], bf[4][2];
            #pragma unroll
            for (int f = 0; f < 4; f++) {
                int r0 = wm + f * 16 + g;
                af[f][0] = as[r0 * 36 + w0];
                af[f][1] = as[(r0 + 8) * 36 + w0];
                af[f][2] = as[r0 * 36 + w0 + 4];
                af[f][3] = as[(r0 + 8) * 36 + w0 + 4];
            }
            #pragma unroll
            for (int j = 0; j < 4; j++) {
                int c0 = wn + j * 8 + g;
                bf[j][0] = bs[c0 * 36 + w0];
                bf[j][1] = bs[c0 * 36 + w0 + 4];
            }
            #pragma unroll
            for (int f = 0; f < 4; f++)
                #pragma unroll
                for (int j = 0; j < 4; j++)
                    mma_f16(acc[f][j], af[f], bf[j]);
        }
        __syncthreads();
    }

    #pragma unroll
    for (int f = 0; f < 4; f++) {
        int gm0 = bm + wm + f * 16 + g;
        #pragma unroll
        for (int j = 0; j < 4; j++) {
            int gn = bn + wn + j * 8 + 2 * l;
            if (gn >= N) continue;
            bool n1 = (gn + 1 < N);
            float b0 = bias ? bias[gn] : 0.f;
            float b1 = (bias && n1) ? bias[gn + 1] : 0.f;
            #pragma unroll
            for (int half_i = 0; half_i < 2; half_i++) {
                int gm = gm0 + half_i * 8;
                if (gm >= M) continue;
                float v0 = acc[f][j][half_i * 2 + 0] + b0;
                float v1 = acc[f][j][half_i * 2 + 1] + b1;
                if (ACT == 1) { v0 = geluf(v0); v1 = geluf(v1); }
                else if (ACT == 2) { v0 = softplusf(v0); v1 = softplusf(v1); }
                if (res) {
                    v0 += res[(size_t)gm * ldres + gn];
                    if (n1) v1 += res[(size_t)gm * ldres + gn + 1];
                }
                if (WF32) {
                    C[(size_t)gm * ldc + gn] = v0;
                    if (n1) C[(size_t)gm * ldc + gn + 1] = v1;
                }
                if (WH16) {
                    Ch[(size_t)gm * ldc + gn] = __float2half(v0);
                    if (n1) Ch[(size_t)gm * ldc + gn + 1] = __float2half(v1);
                }
            }
        }
    }
}

// ---------------- LayerNorm (fp32 in, fp16 out) ----------
__global__ void layernorm_kernel(const float* __restrict__ x,
                                 const float* __restrict__ g,
                                 const float* __restrict__ b,
                                 __half* __restrict__ out) {
    int row = blockIdx.x;
    const float* xr = x + (size_t)row * DD;
    float s = 0.f, s2 = 0.f;
    for (int i = threadIdx.x; i < DD; i += blockDim.x) {
        float v = xr[i];
        s += v; s2 += v * v;
    }
    __shared__ float shm[2][33];
    #pragma unroll
    for (int off = 16; off; off >>= 1) {
        s  += __shfl_xor_sync(0xffffffffu, s,  off);
        s2 += __shfl_xor_sync(0xffffffffu, s2, off);
    }
    int lane = threadIdx.x & 31, w = threadIdx.x >> 5;
    if (lane == 0) { shm[0][w] = s; shm[1][w] = s2; }
    __syncthreads();
    int nw = blockDim.x >> 5;
    if (w == 0) {
        s  = (lane < nw) ? shm[0][lane] : 0.f;
        s2 = (lane < nw) ? shm[1][lane] : 0.f;
        #pragma unroll
        for (int off = 16; off; off >>= 1) {
            s  += __shfl_xor_sync(0xffffffffu, s,  off);
            s2 += __shfl_xor_sync(0xffffffffu, s2, off);
        }
        if (lane == 0) { shm[0][32] = s; shm[1][32] = s2; }
    }
    __syncthreads();
    float mu  = shm[0][32] * (1.0f / DD);
    float var = shm[1][32] * (1.0f / DD) - mu * mu;
    float inv = rsqrtf(var + 1e-5f);
    __half* orow = out + (size_t)row * DD;
    for (int i = threadIdx.x; i < DD; i += blockDim.x)
        orow[i] = __float2half((xr[i] - mu) * inv * g[i] + b[i]);
}

// ---------------- causal conv (K=4) + bias + silu -> fp16 only ----------
template<int DIR>
__global__ void conv_silu_kernel(const __half* __restrict__ xzx,
                                 const float* __restrict__ cw,
                                 const float* __restrict__ cb,
                                 __half* __restrict__ out_h) {
    int idx = blockIdx.x * blockDim.x + threadIdx.x;
    if (idx >= ROWS * DI) return;
    int d = idx % DI;
    int t = (idx / DI) % LL;
    int b = idx / (DI * LL);
    float acc = cb[d];
    #pragma unroll
    for (int k = 0; k < KK; k++) {
        int tt = (DIR > 0) ? (t - (KK - 1) + k) : (t + (KK - 1) - k);
        if (tt >= 0 && tt < LL)
            acc += __half2float(xzx[((size_t)(b * LL + tt)) * LDXZ + d]) * cw[d * KK + k];
    }
    out_h[idx] = __float2half(siluf(acc));
}

// ---------------- chunked parallel scan (x from fp16 xch) ----------------
template<int DIR>
__global__ void scan_part1(const float* __restrict__ dt,
                           const __half* __restrict__ xch,
                           const float* __restrict__ dbc,
                           const float* __restrict__ A_log,
                           float* __restrict__ hp, float* __restrict__ pe) {
    int gidx = blockIdx.x * 16 + (threadIdx.x >> 4);
    int s = threadIdx.x & 15;
    int c = gidx % NC;
    int d = (gidx / NC) % DI;
    int b = gidx / (NC * DI);
    if (b >= BB) return;
    float Aval = -__expf(A_log[d * DS + s]);
    float h = 0.f, p = 1.f;
    size_t base = (size_t)b * LL;
    int u0 = c * CL;
    for (int i = 0; i < CL; i++) {
        int u = u0 + i;
        int t = (DIR > 0) ? u : (LL - 1 - u);
        size_t row = base + t;
        float dtv = dt[row * DI + d];
        float xv  = __half2float(xch[row * DI + d]);
        float Bv  = dbc[row * DBC_W + DTR + s];
        float e = __expf(dtv * Aval);
        h = e * h + dtv * xv * Bv;
        p *= e;
    }
    size_t o = (size_t)gidx * DS + s;
    hp[o] = h;
    pe[o] = p;
}

__global__ void scan_part2(const float* __restrict__ hp,
                           const float* __restrict__ pe,
                           float* __restrict__ h0) {
    int i = blockIdx.x * blockDim.x + threadIdx.x;
    if (i >= BB * DI * DS) return;
    int s = i & (DS - 1);
    int gd = i >> 4;
    float H = 0.f;
    #pragma unroll
    for (int c = 0; c < NC; c++) {
        size_t o = ((size_t)gd * NC + c) * DS + s;
        h0[o] = H;
        H = hp[o] + H * pe[o];
    }
}

template<int DIR>
__global__ void scan_part3(const float* __restrict__ dt,
                           const __half* __restrict__ xch,
                           const float* __restrict__ dbc,
                           const __half* __restrict__ zp,
                           const float* __restrict__ A_log,
                           const float* __restrict__ Dp,
                           const float* __restrict__ h0,
                           __half* __restrict__ y) {
    int gidx = blockIdx.x * 16 + (threadIdx.x >> 4);
    int s = threadIdx.x & 15;
    int c = gidx % NC;
    int d = (gidx / NC) % DI;
    int b = gidx / (NC * DI);
    if (b >= BB) return;
    float Aval = -__expf(A_log[d * DS + s]);
    float Dv = Dp[d];
    float h = h0[(size_t)gidx * DS + s];
    size_t base = (size_t)b * LL;
    int u0 = c * CL;
    for (int i = 0; i < CL; i++) {
        int u = u0 + i;
        int t = (DIR > 0) ? u : (LL - 1 - u);
        size_t row = base + t;
        float dtv = dt[row * DI + d];
        float xv  = __half2float(xch[row * DI + d]);
        float Bv  = dbc[row * DBC_W + DTR + s];
        float Cv  = dbc[row * DBC_W + DTR + DS + s];
        float e = __expf(dtv * Aval);
        h = e * h + dtv * xv * Bv;
        float part = h * Cv;
        #pragma unroll
        for (int off = 8; off; off >>= 1)
            part += __shfl_xor_sync(0xffffffffu, part, off);
        if (s == 0) {
            float zv = __half2float(zp[row * LDXZ + d]);
            y[row * DI + d] = __float2half((part + xv * Dv) * siluf(zv));
        }
    }
}

// ---------------- host side ----------------
static void* symv(const void* s) {
    void* p = nullptr;
    cudaGetSymbolAddress(&p, s);
    return p;
}

template<int ACT, bool CAT, bool WF32, bool WH16>
static void launch_hgemm(cudaStream_t st,
                         const __half* A, const __half* A2, int ksplit, int lda,
                         const __half* W, int ldw,
                         float* C, __half* Ch, int ldc,
                         int M, int N, int Kd,
                         const float* bias, const float* res, int ldres) {
    static bool attr_set = false;
    if (!attr_set) {
        cudaFuncSetAttribute(hgemm<ACT, CAT, WF32, WH16>,
                             cudaFuncAttributeMaxDynamicSharedMemorySize, SMEM_GEMM);
        attr_set = true;
    }
    dim3 grid((N + GBN - 1) / GBN, (M + GBM - 1) / GBM);
    hgemm<ACT, CAT, WF32, WH16><<<grid, 256, SMEM_GEMM, st>>>(
        A, A2, ksplit, lda, W, ldw, C, Ch, ldc, M, N, Kd, bias, res, ldres);
}

template<int DIR>
static void run_mamba_tail(cudaStream_t st,
                           const __half* xzx, const __half* zp,
                           const float* conv_w, const float* conv_b,
                           const __half* xproj_wh, const __half* dt_wh, const float* dt_b,
                           const float* A_log, const float* Dp,
                           __half* xch, float* dbc, __half* dbch,
                           float* dt, __half* yh,
                           float* hp, float* pe, float* h0) {
    conv_silu_kernel<DIR><<<(ROWS * DI + 255) / 256, 256, 0, st>>>(xzx, conv_w, conv_b, xch);
    launch_hgemm<0, false, true, true>(st, xch, nullptr, 0, DI, xproj_wh, DI,
                                       dbc, dbch, DBC_W, ROWS, DBC_W, DI, nullptr, nullptr, 0);
    launch_hgemm<2, false, true, false>(st, dbch, nullptr, 0, DBC_W, dt_wh, DTR,
                                        dt, nullptr, DI, ROWS, DI, DTR, dt_b, nullptr, 0);
    scan_part1<DIR><<<(BB * DI * NC) / 16, 256, 0, st>>>(dt, xch, dbc, A_log, hp, pe);
    scan_part2<<<(BB * DI * DS + 255) / 256, 256, 0, st>>>(hp, pe, h0);
    scan_part3<DIR><<<(BB * DI * NC) / 16, 256, 0, st>>>(dt, xch, dbc, zp, A_log, Dp, h0, yh);
}

extern "C" void kernel_launch(void* const* d_in, const int* in_sizes, int n_in,
                              void* d_out, int out_size) {
    const float* x        = (const float*)d_in[0];
    const float* norm_g   = (const float*)d_in[1];
    const float* norm_b   = (const float*)d_in[2];
    const float* f_in_w   = (const float*)d_in[3];
    const float* f_conv_w = (const float*)d_in[4];
    const float* f_conv_b = (const float*)d_in[5];
    const float* f_xproj_w= (const float*)d_in[6];
    const float* f_dt_w   = (const float*)d_in[7];
    const float* f_dt_b   = (const float*)d_in[8];
    const float* f_A_log  = (const float*)d_in[9];
    const float* f_D      = (const float*)d_in[10];
    const float* f_out_w  = (const float*)d_in[11];
    const float* b_in_w   = (const float*)d_in[12];
    const float* b_conv_w = (const float*)d_in[13];
    const float* b_conv_b = (const float*)d_in[14];
    const float* b_xproj_w= (const float*)d_in[15];
    const float* b_dt_w   = (const float*)d_in[16];
    const float* b_dt_b   = (const float*)d_in[17];
    const float* b_A_log  = (const float*)d_in[18];
    const float* b_D      = (const float*)d_in[19];
    const float* b_out_w  = (const float*)d_in[20];
    const float* mix_w    = (const float*)d_in[21];
    const float* mix_b    = (const float*)d_in[22];
    const float* ffn_w1   = (const float*)d_in[23];
    const float* ffn_b1   = (const float*)d_in[24];
    const float* ffn_w2   = (const float*)d_in[25];
    const float* ffn_b2   = (const float*)d_in[26];
    const float* ffn_norm_g = (const float*)d_in[27];
    const float* ffn_norm_b = (const float*)d_in[28];

    __half* xz_h  = (__half*)symv(g_xz_h);
    __half* xn_h  = (__half*)symv(g_xn_h);
    __half* xch_f = (__half*)symv(g_xch_f);
    float*  dbc_f = (float*) symv(g_dbc_f);
    __half* dbch_f= (__half*)symv(g_dbch_f);
    float*  dt_f  = (float*) symv(g_dt_f);
    __half* yh_f  = (__half*)symv(g_yh_f);
    __half* xch_b = (__half*)symv(g_xch_b);
    float*  dbc_b = (float*) symv(g_dbc_b);
    __half* dbch_b= (__half*)symv(g_dbch_b);
    float*  dt_bs = (float*) symv(g_dt_b);
    __half* yh_b  = (__half*)symv(g_yh_b);
    float*  h     = (float*) symv(g_h);
    __half* hn_h  = (__half*)symv(g_hn_h);
    __half* ff1_h = (__half*)symv(g_ff1_h);
    __half* wh    = (__half*)symv(g_wh);
    __half* owT   = (__half*)symv(g_owT);
    __half* wcomb = (__half*)symv(g_wcomb);
    float*  hp_f  = (float*) symv(g_hp_f);
    float*  pe_f  = (float*) symv(g_pe_f);
    float*  h0_f  = (float*) symv(g_h0_f);
    float*  hp_b  = (float*) symv(g_hp_b);
    float*  pe_b  = (float*) symv(g_pe_b);
    float*  h0_b  = (float*) symv(g_h0_b);
    float*  p0    = (float*) symv(g_p0);
    float*  p1    = (float*) symv(g_p1);
    float*  out   = (float*)d_out;

    static cudaStream_t s2 = nullptr;
    static cudaEvent_t evStart = nullptr, evCvt = nullptr, evB = nullptr,
                       evW = nullptr, evM2 = nullptr, evF = nullptr, evF2 = nullptr;
    if (!s2) {
        cudaStreamCreateWithFlags(&s2, cudaStreamNonBlocking);
        cudaEventCreateWithFlags(&evStart, cudaEventDisableTiming);
        cudaEventCreateWithFlags(&evCvt, cudaEventDisableTiming);
        cudaEventCreateWithFlags(&evB, cudaEventDisableTiming);
        cudaEventCreateWithFlags(&evW, cudaEventDisableTiming);
        cudaEventCreateWithFlags(&evM2, cudaEventDisableTiming);
        cudaEventCreateWithFlags(&evF, cudaEventDisableTiming);
        cudaEventCreateWithFlags(&evF2, cudaEventDisableTiming);
    }

    // fork s2 from main (legal: event recorded on capturing stream first)
    cudaEventRecord(evStart, 0);
    cudaStreamWaitEvent(s2, evStart, 0);

    // 0) weight fp16 conversion on s2 (hidden under LN1); launches #1,#2
    CvtSegs<6> sa;
    sa.s[0] = f_in_w;    sa.d[0] = wh + OFF_FIN;  sa.n[0] = W_IN;
    sa.s[1] = b_in_w;    sa.d[1] = wh + OFF_BIN;  sa.n[1] = W_IN;
    sa.s[2] = f_xproj_w; sa.d[2] = wh + OFF_FXP;  sa.n[2] = W_XP;
    sa.s[3] = b_xproj_w; sa.d[3] = wh + OFF_BXP;  sa.n[3] = W_XP;
    sa.s[4] = f_dt_w;    sa.d[4] = wh + OFF_FDT;  sa.n[4] = W_DT;
    sa.s[5] = b_dt_w;    sa.d[5] = wh + OFF_BDT;  sa.n[5] = W_DT;
    cvt_weights<6><<<1024, 256, 0, s2>>>(sa);
    CvtSegs<3> sb;
    sb.s[0] = mix_w;     sb.d[0] = wh + OFF_MIX;  sb.n[0] = W_MIX;
    sb.s[1] = ffn_w1;    sb.d[1] = wh + OFF_FF1;  sb.n[1] = W_FF1;
    sb.s[2] = ffn_w2;    sb.d[2] = wh + OFF_FF2;  sb.n[2] = W_FF2;
    cvt_weights<3><<<1024, 256, 0, s2>>>(sb);
    cudaEventRecord(evCvt, s2);

    // 1) layernorm 1 -> fp16 (launch #3, main, concurrent with cvt)
    layernorm_kernel<<<ROWS, 256>>>(x, norm_g, norm_b, xn_h);
    cudaStreamWaitEvent(0, evCvt, 0);

    // 2) merged fwd+bwd in_proj (launch #4 — profiled)
    launch_hgemm<0, false, false, true>(0, xn_h, nullptr, 0, DD, wh + OFF_FIN, DD,
                                        nullptr, xz_h, LDXZ, ROWS, LDXZ, DD, nullptr, nullptr, 0);
    cudaEventRecord(evB, 0);

    // s2: combined-weight prep (after cvt, same stream)
    transpose_w<<<dim3(DI / 32, DD / 32, 2), dim3(32, 32), 0, s2>>>(f_out_w, b_out_w, owT);
    launch_hgemm<0, false, false, true>(s2, wh + OFF_MIX, nullptr, 0, 2 * DD,
                                        owT, DD, nullptr, wcomb, 2 * DI,
                                        DD, DI, DD, nullptr, nullptr, 0);
    launch_hgemm<0, false, false, true>(s2, wh + OFF_MIX + DD, nullptr, 0, 2 * DD,
                                        owT + (size_t)DI * DD, DD, nullptr, wcomb + DI, 2 * DI,
                                        DD, DI, DD, nullptr, nullptr, 0);
    cudaEventRecord(evW, s2);

    // s2: wait for in_proj, run bwd branch
    cudaStreamWaitEvent(s2, evB, 0);
    run_mamba_tail<-1>(s2, xz_h + 2 * DI, xz_h + 3 * DI,
                       b_conv_w, b_conv_b, wh + OFF_BXP, wh + OFF_BDT, b_dt_b,
                       b_A_log, b_D,
                       xch_b, dbc_b, dbch_b, dt_bs, yh_b,
                       hp_b, pe_b, h0_b);
    // s2: mix partial-B = yh_b @ Wb'^T (all inputs s2-resident)
    launch_hgemm<0, false, true, false>(s2, yh_b, nullptr, 0, DI, wcomb + DI, 2 * DI,
                                        p1, nullptr, DD, ROWS, DD, DI, nullptr, nullptr, 0);
    cudaEventRecord(evM2, s2);

    // main: fwd branch
    run_mamba_tail<1>(0, xz_h + 0, xz_h + DI,
                      f_conv_w, f_conv_b, wh + OFF_FXP, wh + OFF_FDT, f_dt_b,
                      f_A_log, f_D,
                      xch_f, dbc_f, dbch_f, dt_f, yh_f,
                      hp_f, pe_f, h0_f);

    // main: mix partial-A = yh_f @ Wf'^T (needs wcomb from s2)
    cudaStreamWaitEvent(0, evW, 0);
    launch_hgemm<0, false, true, false>(0, yh_f, nullptr, 0, DI, wcomb, 2 * DI,
                                        p0, nullptr, DD, ROWS, DD, DI, nullptr, nullptr, 0);
    // reduce: h = p0 + p1 + mix_b + x
    cudaStreamWaitEvent(0, evM2, 0);
    reduce2_kernel<<<(ROWS * DD / 4 + 255) / 256, 256>>>(p0, p1, mix_b, x, h);

    // layernorm 2 -> fp16
    layernorm_kernel<<<ROWS, 256>>>(h, ffn_norm_g, ffn_norm_b, hn_h);

    // FFN1 + bias + gelu -> fp16
    launch_hgemm<1, false, false, true>(0, hn_h, nullptr, 0, DD, wh + OFF_FF1, DD,
                                        nullptr, ff1_h, 4 * DD, ROWS, 4 * DD, DD, ffn_b1, nullptr, 0);

    // FFN2 split-K across streams
    cudaEventRecord(evF, 0);
    cudaStreamWaitEvent(s2, evF, 0);
    launch_hgemm<0, false, true, false>(s2, ff1_h + 2 * DD, nullptr, 0, 4 * DD,
                                        wh + OFF_FF2 + 2 * DD, 4 * DD,
                                        p1, nullptr, DD, ROWS, DD, 2 * DD, nullptr, nullptr, 0);
    cudaEventRecord(evF2, s2);
    launch_hgemm<0, false, true, false>(0, ff1_h, nullptr, 0, 4 * DD,
                                        wh + OFF_FF2, 4 * DD,
                                        p0, nullptr, DD, ROWS, DD, 2 * DD, nullptr, nullptr, 0);
    cudaStreamWaitEvent(0, evF2, 0);
    // reduce: out = p0 + p1 + ffn_b2 + h
    reduce2_kernel<<<(ROWS * DD / 4 + 255) / 256, 256>>>(p0, p1, ffn_b2, h, out);
}

// round 15
// speedup vs baseline: 1.1398x; 1.1398x over previous
#include <cuda_runtime.h>
#include <cuda_fp16.h>
#include <cstdint>

// Problem constants
#define BB 2
#define LL 2048
#define DD 768
#define DI 1536
#define DS 16
#define DTR 48
#define KK 4
#define ROWS (BB*LL)            // 4096
#define DBC_W (DTR + 2*DS)      // 80
#define LDXZ (4*DI)             // 6144
#define NC 16                   // scan chunks
#define CL (LL/NC)              // 128 steps per chunk
#define DBLK (DI/16)            // 96 d-blocks of 16

// ---------------- scratch (device globals; allocation-free) ----------------
__device__ __align__(16) __half g_xz_h [(size_t)ROWS*LDXZ];
__device__ __align__(16) __half g_xn_h [ROWS*DD];
__device__ __align__(16) __half g_xch_f[(size_t)ROWS*DI];
__device__ __align__(16) float  g_dbc_f[(size_t)ROWS*DBC_W];
__device__ __align__(16) __half g_dbch_f[(size_t)ROWS*DBC_W];
__device__ __align__(16) float  g_dt_f [(size_t)ROWS*DI];
__device__ __align__(16) __half g_yh_f [(size_t)ROWS*DI];
__device__ __align__(16) __half g_xch_b[(size_t)ROWS*DI];
__device__ __align__(16) float  g_dbc_b[(size_t)ROWS*DBC_W];
__device__ __align__(16) __half g_dbch_b[(size_t)ROWS*DBC_W];
__device__ __align__(16) float  g_dt_b [(size_t)ROWS*DI];
__device__ __align__(16) __half g_yh_b [(size_t)ROWS*DI];
__device__ __align__(16) float  g_h    [ROWS*DD];
__device__ __align__(16) __half g_hn_h [ROWS*DD];
__device__ __align__(16) __half g_ff1_h[(size_t)ROWS*4*DD];
__device__ __align__(16) float  g_p0   [ROWS*DD];   // split-K partials
__device__ __align__(16) float  g_p1   [ROWS*DD];

// chunked-scan intermediates (per branch)
#define SCAN_ST (BB*DI*NC*DS)   // 786432
__device__ __align__(16) float g_hp_f[SCAN_ST];
__device__ __align__(16) float g_pe_f[SCAN_ST];
__device__ __align__(16) float g_h0_f[SCAN_ST];
__device__ __align__(16) float g_hp_b[SCAN_ST];
__device__ __align__(16) float g_pe_b[SCAN_ST];
__device__ __align__(16) float g_h0_b[SCAN_ST];

// fused out_proj+mix: transposed out weights + combined weights
__device__ __align__(16) __half g_owT  [2*(size_t)DI*DD];     // fowT | bowT
__device__ __align__(16) __half g_wcomb[(size_t)DD*2*DI];     // [768 x 3072]

// fp16 weight scratch
#define W_IN   (2*DI*DD)
#define W_XP   (DBC_W*DI)
#define W_DT   (DI*DTR)
#define W_MIX  (DD*2*DD)
#define W_FF1  (4*DD*DD)
#define W_FF2  (DD*4*DD)
#define OFF_FIN  0
#define OFF_BIN  (OFF_FIN + W_IN)
#define OFF_FXP  (OFF_BIN + W_IN)
#define OFF_BXP  (OFF_FXP + W_XP)
#define OFF_FDT  (OFF_BXP + W_XP)
#define OFF_BDT  (OFF_FDT + W_DT)
#define OFF_MIX  (OFF_BDT + W_DT)
#define OFF_FF1  (OFF_MIX + W_MIX)
#define OFF_FF2  (OFF_FF1 + W_FF1)
#define W_TOTAL  (OFF_FF2 + W_FF2)
__device__ __align__(16) __half g_wh[W_TOTAL];

// ---------------- helpers ----------------
__device__ __forceinline__ float siluf(float x) {
    return x / (1.0f + __expf(-x));
}
__device__ __forceinline__ float geluf(float x) {
    float x3 = x * x * x;
    return 0.5f * x * (1.0f + tanhf(0.7978845608028654f * (x + 0.044715f * x3)));
}
__device__ __forceinline__ float softplusf(float x) {
    if (x > 20.0f) return x;
    return log1pf(__expf(x));
}

__device__ __forceinline__ void cpa16(uint32_t dst, const void* src, bool v) {
    int sz = v ? 16 : 0;
    asm volatile("cp.async.cg.shared.global [%0], [%1], 16, %2;"
        :: "r"(dst), "l"(src), "r"(sz) : "memory");
}
#define CP_COMMIT() asm volatile("cp.async.commit_group;" ::: "memory")
#define CP_WAIT(n)  asm volatile("cp.async.wait_group %0;" :: "n"(n) : "memory")

__device__ __forceinline__ uint32_t smem_u32(const void* p) {
    uint32_t a;
    asm("{ .reg .u64 t; cvta.to.shared.u64 t, %1; cvt.u32.u64 %0, t; }" : "=r"(a) : "l"(p));
    return a;
}
__device__ __forceinline__ void mma_f16(float* d, const uint32_t* a, const uint32_t* b) {
    asm volatile("mma.sync.aligned.m16n8k16.row.col.f32.f16.f16.f32 "
                 "{%0,%1,%2,%3}, {%4,%5,%6,%7}, {%8,%9}, {%0,%1,%2,%3};"
                 : "+f"(d[0]), "+f"(d[1]), "+f"(d[2]), "+f"(d[3])
                 : "r"(a[0]), "r"(a[1]), "r"(a[2]), "r"(a[3]),
                   "r"(b[0]), "r"(b[1]));
}

// ---------------- one-shot weight conversion fp32 -> fp16 ----------------
template<int NS>
struct CvtSegs {
    const float* s[NS];
    __half* d[NS];
    int n[NS];
};
template<int NS>
__global__ void cvt_weights(CvtSegs<NS> sg) {
    int stride = gridDim.x * blockDim.x;
    int i0 = blockIdx.x * blockDim.x + threadIdx.x;
    #pragma unroll
    for (int k = 0; k < NS; k++) {
        const float4* s4 = (const float4*)sg.s[k];
        __half2* d2 = (__half2*)sg.d[k];
        int n4 = sg.n[k] >> 2;
        for (int i = i0; i < n4; i += stride) {
            float4 v = s4[i];
            d2[2*i]   = __floats2half2_rn(v.x, v.y);
            d2[2*i+1] = __floats2half2_rn(v.z, v.w);
        }
    }
}

// ---------------- out_w transpose: fp32 [768x1536] -> fp16 [1536x768] -----
__global__ void transpose_w(const float* __restrict__ s0, const float* __restrict__ s1,
                            __half* __restrict__ dst) {
    __shared__ __half tile[32][33];
    const float* src = blockIdx.z ? s1 : s0;
    __half* d = dst + (size_t)blockIdx.z * DI * DD;
    int kx = blockIdx.x * 32 + threadIdx.x;   // k in [0,1536)
    int jy = blockIdx.y * 32 + threadIdx.y;   // j in [0,768)
    tile[threadIdx.y][threadIdx.x] = __float2half(src[(size_t)jy * DI + kx]);
    __syncthreads();
    int k = blockIdx.x * 32 + threadIdx.y;
    int j = blockIdx.y * 32 + threadIdx.x;
    d[(size_t)k * DD + j] = tile[threadIdx.x][threadIdx.y];
}

// ---------------- split-K reduce: C = p0 + p1 + bias + res ----------------
__global__ void reduce2_kernel(const float* __restrict__ p0,
                               const float* __restrict__ p1,
                               const float* __restrict__ bias,
                               const float* __restrict__ res,
                               float* __restrict__ C) {
    int i = blockIdx.x * blockDim.x + threadIdx.x;   // float4 index
    if (i * 4 >= ROWS * DD) return;
    float4 a = ((const float4*)p0)[i];
    float4 b = ((const float4*)p1)[i];
    float4 r = ((const float4*)res)[i];
    int col = (i * 4) % DD;
    a.x += b.x + bias[col + 0] + r.x;
    a.y += b.y + bias[col + 1] + r.y;
    a.z += b.z + bias[col + 2] + r.z;
    a.w += b.w + bias[col + 3] + r.w;
    ((float4*)C)[i] = a;
}

// ================= fp16 mma.sync GEMM (fp32 accumulate) =================
#define GBM 128
#define GBN 128
#define GBK 64
#define KH 72
#define STAGE_B (GBM*KH*2)
#define SMEM_GEMM (4*STAGE_B)

template<int ACT, bool CAT, bool WF32, bool WH16>
__global__ __launch_bounds__(256, 2)
void hgemm(const __half* __restrict__ A, const __half* __restrict__ A2,
           int ksplit, int lda,
           const __half* __restrict__ W, int ldw,
           float* __restrict__ C, __half* __restrict__ Ch, int ldc,
           int M, int N, int Kd,
           const float* __restrict__ bias,
           const float* __restrict__ res, int ldres) {
    extern __shared__ __half smh[];
    __half* As = smh;
    __half* Bs = smh + 2 * GBM * KH;
    uint32_t sA = smem_u32(As);
    uint32_t sB = smem_u32(Bs);

    int tid = threadIdx.x;
    int lane = tid & 31, wid = tid >> 5;
    int bm = blockIdx.y * GBM, bn = blockIdx.x * GBN;
    int wm = (wid & 1) * 64, wn = (wid >> 1) * 32;
    int g = lane >> 2, l = lane & 3;

    float acc[4][4][4];
    #pragma unroll
    for (int f = 0; f < 4; f++)
        #pragma unroll
        for (int j = 0; j < 4; j++)
            #pragma unroll
            for (int c = 0; c < 4; c++) acc[f][j][c] = 0.f;

    auto load_stage = [&](int buf, int kt) {
        int k0 = kt * GBK;
        const __half* srcA = A;
        int kbase = k0;
        if (CAT && k0 >= ksplit) { srcA = A2; kbase = k0 - ksplit; }
        #pragma unroll
        for (int t = 0; t < 4; t++) {
            int c = tid + t * 256;
            int row = c >> 3, seg = c & 7;
            bool kv = (k0 + seg * 8) < Kd;
            int gm = bm + row;
            bool va = kv && (gm < M);
            cpa16(sA + buf * STAGE_B + row * (KH*2) + seg * 16,
                  srcA + (size_t)(va ? gm : 0) * lda + (va ? (kbase + seg * 8) : 0), va);
            int gn = bn + row;
            bool vb = kv && (gn < N);
            cpa16(sB + buf * STAGE_B + row * (KH*2) + seg * 16,
                  W + (size_t)(vb ? gn : 0) * ldw + (vb ? (k0 + seg * 8) : 0), vb);
        }
        CP_COMMIT();
    };

    const int NT = (Kd + GBK - 1) / GBK;
    load_stage(0, 0);

    for (int kt = 0; kt < NT; kt++) {
        int buf = kt & 1;
        if (kt + 1 < NT) {
            load_stage(buf ^ 1, kt + 1);
            CP_WAIT(1);
        } else {
            CP_WAIT(0);
        }
        __syncthreads();

        const uint32_t* as = (const uint32_t*)(As + buf * GBM * KH);
        const uint32_t* bs = (const uint32_t*)(Bs + buf * GBN * KH);
        #pragma unroll
        for (int s = 0; s < 4; s++) {
            int w0 = s * 8 + l;
            uint32_t af[4][4], bf[4][2];
            #pragma unroll
            for (int f = 0; f < 4; f++) {
                int r0 = wm + f * 16 + g;
                af[f][0] = as[r0 * 36 + w0];
                af[f][1] = as[(r0 + 8) * 36 + w0];
                af[f][2] = as[r0 * 36 + w0 + 4];
                af[f][3] = as[(r0 + 8) * 36 + w0 + 4];
            }
            #pragma unroll
            for (int j = 0; j < 4; j++) {
                int c0 = wn + j * 8 + g;
                bf[j][0] = bs[c0 * 36 + w0];
                bf[j][1] = bs[c0 * 36 + w0 + 4];
            }
            #pragma unroll
            for (int f = 0; f < 4; f++)
                #pragma unroll
                for (int j = 0; j < 4; j++)
                    mma_f16(acc[f][j], af[f], bf[j]);
        }
        __syncthreads();
    }

    #pragma unroll
    for (int f = 0; f < 4; f++) {
        int gm0 = bm + wm + f * 16 + g;
        #pragma unroll
        for (int j = 0; j < 4; j++) {
            int gn = bn + wn + j * 8 + 2 * l;
            if (gn >= N) continue;
            bool n1 = (gn + 1 < N);
            float b0 = bias ? bias[gn] : 0.f;
            float b1 = (bias && n1) ? bias[gn + 1] : 0.f;
            #pragma unroll
            for (int half_i = 0; half_i < 2; half_i++) {
                int gm = gm0 + half_i * 8;
                if (gm >= M) continue;
                float v0 = acc[f][j][half_i * 2 + 0] + b0;
                float v1 = acc[f][j][half_i * 2 + 1] + b1;
                if (ACT == 1) { v0 = geluf(v0); v1 = geluf(v1); }
                else if (ACT == 2) { v0 = softplusf(v0); v1 = softplusf(v1); }
                if (res) {
                    v0 += res[(size_t)gm * ldres + gn];
                    if (n1) v1 += res[(size_t)gm * ldres + gn + 1];
                }
                if (WF32) {
                    C[(size_t)gm * ldc + gn] = v0;
                    if (n1) C[(size_t)gm * ldc + gn + 1] = v1;
                }
                if (WH16) {
                    Ch[(size_t)gm * ldc + gn] = __float2half(v0);
                    if (n1) Ch[(size_t)gm * ldc + gn + 1] = __float2half(v1);
                }
            }
        }
    }
}

// ---------------- LayerNorm (fp32 in, fp16 out) ----------
__global__ void layernorm_kernel(const float* __restrict__ x,
                                 const float* __restrict__ g,
                                 const float* __restrict__ b,
                                 __half* __restrict__ out) {
    int row = blockIdx.x;
    const float* xr = x + (size_t)row * DD;
    float s = 0.f, s2 = 0.f;
    for (int i = threadIdx.x; i < DD; i += blockDim.x) {
        float v = xr[i];
        s += v; s2 += v * v;
    }
    __shared__ float shm[2][33];
    #pragma unroll
    for (int off = 16; off; off >>= 1) {
        s  += __shfl_xor_sync(0xffffffffu, s,  off);
        s2 += __shfl_xor_sync(0xffffffffu, s2, off);
    }
    int lane = threadIdx.x & 31, w = threadIdx.x >> 5;
    if (lane == 0) { shm[0][w] = s; shm[1][w] = s2; }
    __syncthreads();
    int nw = blockDim.x >> 5;
    if (w == 0) {
        s  = (lane < nw) ? shm[0][lane] : 0.f;
        s2 = (lane < nw) ? shm[1][lane] : 0.f;
        #pragma unroll
        for (int off = 16; off; off >>= 1) {
            s  += __shfl_xor_sync(0xffffffffu, s,  off);
            s2 += __shfl_xor_sync(0xffffffffu, s2, off);
        }
        if (lane == 0) { shm[0][32] = s; shm[1][32] = s2; }
    }
    __syncthreads();
    float mu  = shm[0][32] * (1.0f / DD);
    float var = shm[1][32] * (1.0f / DD) - mu * mu;
    float inv = rsqrtf(var + 1e-5f);
    __half* orow = out + (size_t)row * DD;
    for (int i = threadIdx.x; i < DD; i += blockDim.x)
        orow[i] = __float2half((xr[i] - mu) * inv * g[i] + b[i]);
}

// ---------------- causal conv (K=4) + bias + silu -> fp16 only ----------
template<int DIR>
__global__ void conv_silu_kernel(const __half* __restrict__ xzx,
                                 const float* __restrict__ cw,
                                 const float* __restrict__ cb,
                                 __half* __restrict__ out_h) {
    int idx = blockIdx.x * blockDim.x + threadIdx.x;
    if (idx >= ROWS * DI) return;
    int d = idx % DI;
    int t = (idx / DI) % LL;
    int b = idx / (DI * LL);
    float acc = cb[d];
    #pragma unroll
    for (int k = 0; k < KK; k++) {
        int tt = (DIR > 0) ? (t - (KK - 1) + k) : (t + (KK - 1) - k);
        if (tt >= 0 && tt < LL)
            acc += __half2float(xzx[((size_t)(b * LL + tt)) * LDXZ + d]) * cw[d * KK + k];
    }
    out_h[idx] = __float2half(siluf(acc));
}

// ---------------- chunked parallel scan (d-coalesced block mapping) -------
// Block = (b, c, 16 consecutive d); thread: g = tid>>4 (local d), s = tid&15.
// All per-d scalars (dt/x/z) are adjacent across the block's groups and B/C
// rows are shared by all 16 groups -> minimal L2 sector traffic.
template<int DIR>
__global__ void scan_part1(const float* __restrict__ dt,
                           const __half* __restrict__ xch,
                           const float* __restrict__ dbc,
                           const float* __restrict__ A_log,
                           float* __restrict__ hp, float* __restrict__ pe) {
    int bid = blockIdx.x;
    int dblk = bid % DBLK;
    int c = (bid / DBLK) % NC;
    int b = bid / (DBLK * NC);
    int s = threadIdx.x & 15;
    int d = dblk * 16 + (threadIdx.x >> 4);
    float Aval = -__expf(A_log[d * DS + s]);
    float h = 0.f, p = 1.f;
    size_t base = (size_t)b * LL;
    int u0 = c * CL;
    for (int i = 0; i < CL; i++) {
        int u = u0 + i;
        int t = (DIR > 0) ? u : (LL - 1 - u);
        size_t row = base + t;
        float dtv = dt[row * DI + d];
        float xv  = __half2float(xch[row * DI + d]);
        float Bv  = dbc[row * DBC_W + DTR + s];
        float e = __expf(dtv * Aval);
        h = e * h + dtv * xv * Bv;
        p *= e;
    }
    size_t o = (((size_t)(b * DI + d)) * NC + c) * DS + s;
    hp[o] = h;
    pe[o] = p;
}

__global__ void scan_part2(const float* __restrict__ hp,
                           const float* __restrict__ pe,
                           float* __restrict__ h0) {
    int i = blockIdx.x * blockDim.x + threadIdx.x;
    if (i >= BB * DI * DS) return;
    int s = i & (DS - 1);
    int gd = i >> 4;
    float H = 0.f;
    #pragma unroll
    for (int c = 0; c < NC; c++) {
        size_t o = ((size_t)gd * NC + c) * DS + s;
        h0[o] = H;
        H = hp[o] + H * pe[o];
    }
}

template<int DIR>
__global__ void scan_part3(const float* __restrict__ dt,
                           const __half* __restrict__ xch,
                           const float* __restrict__ dbc,
                           const __half* __restrict__ zp,
                           const float* __restrict__ A_log,
                           const float* __restrict__ Dp,
                           const float* __restrict__ h0,
                           __half* __restrict__ y) {
    int bid = blockIdx.x;
    int dblk = bid % DBLK;
    int c = (bid / DBLK) % NC;
    int b = bid / (DBLK * NC);
    int s = threadIdx.x & 15;
    int d = dblk * 16 + (threadIdx.x >> 4);
    float Aval = -__expf(A_log[d * DS + s]);
    float Dv = Dp[d];
    float h = h0[(((size_t)(b * DI + d)) * NC + c) * DS + s];
    size_t base = (size_t)b * LL;
    int u0 = c * CL;
    for (int i = 0; i < CL; i++) {
        int u = u0 + i;
        int t = (DIR > 0) ? u : (LL - 1 - u);
        size_t row = base + t;
        float dtv = dt[row * DI + d];
        float xv  = __half2float(xch[row * DI + d]);
        float Bv  = dbc[row * DBC_W + DTR + s];
        float Cv  = dbc[row * DBC_W + DTR + DS + s];
        float e = __expf(dtv * Aval);
        h = e * h + dtv * xv * Bv;
        float part = h * Cv;
        #pragma unroll
        for (int off = 8; off; off >>= 1)
            part += __shfl_xor_sync(0xffffffffu, part, off);
        if (s == 0) {
            float zv = __half2float(zp[row * LDXZ + d]);
            y[row * DI + d] = __float2half((part + xv * Dv) * siluf(zv));
        }
    }
}

// ---------------- host side ----------------
static void* symv(const void* s) {
    void* p = nullptr;
    cudaGetSymbolAddress(&p, s);
    return p;
}

template<int ACT, bool CAT, bool WF32, bool WH16>
static void launch_hgemm(cudaStream_t st,
                         const __half* A, const __half* A2, int ksplit, int lda,
                         const __half* W, int ldw,
                         float* C, __half* Ch, int ldc,
                         int M, int N, int Kd,
                         const float* bias, const float* res, int ldres) {
    static bool attr_set = false;
    if (!attr_set) {
        cudaFuncSetAttribute(hgemm<ACT, CAT, WF32, WH16>,
                             cudaFuncAttributeMaxDynamicSharedMemorySize, SMEM_GEMM);
        attr_set = true;
    }
    dim3 grid((N + GBN - 1) / GBN, (M + GBM - 1) / GBM);
    hgemm<ACT, CAT, WF32, WH16><<<grid, 256, SMEM_GEMM, st>>>(
        A, A2, ksplit, lda, W, ldw, C, Ch, ldc, M, N, Kd, bias, res, ldres);
}

template<int DIR>
static void run_mamba_tail(cudaStream_t st,
                           const __half* xzx, const __half* zp,
                           const float* conv_w, const float* conv_b,
                           const __half* xproj_wh, const __half* dt_wh, const float* dt_b,
                           const float* A_log, const float* Dp,
                           __half* xch, float* dbc, __half* dbch,
                           float* dt, __half* yh,
                           float* hp, float* pe, float* h0) {
    conv_silu_kernel<DIR><<<(ROWS * DI + 255) / 256, 256, 0, st>>>(xzx, conv_w, conv_b, xch);
    launch_hgemm<0, false, true, true>(st, xch, nullptr, 0, DI, xproj_wh, DI,
                                       dbc, dbch, DBC_W, ROWS, DBC_W, DI, nullptr, nullptr, 0);
    launch_hgemm<2, false, true, false>(st, dbch, nullptr, 0, DBC_W, dt_wh, DTR,
                                        dt, nullptr, DI, ROWS, DI, DTR, dt_b, nullptr, 0);
    scan_part1<DIR><<<BB * NC * DBLK, 256, 0, st>>>(dt, xch, dbc, A_log, hp, pe);
    scan_part2<<<(BB * DI * DS + 255) / 256, 256, 0, st>>>(hp, pe, h0);
    scan_part3<DIR><<<BB * NC * DBLK, 256, 0, st>>>(dt, xch, dbc, zp, A_log, Dp, h0, yh);
}

extern "C" void kernel_launch(void* const* d_in, const int* in_sizes, int n_in,
                              void* d_out, int out_size) {
    const float* x        = (const float*)d_in[0];
    const float* norm_g   = (const float*)d_in[1];
    const float* norm_b   = (const float*)d_in[2];
    const float* f_in_w   = (const float*)d_in[3];
    const float* f_conv_w = (const float*)d_in[4];
    const float* f_conv_b = (const float*)d_in[5];
    const float* f_xproj_w= (const float*)d_in[6];
    const float* f_dt_w   = (const float*)d_in[7];
    const float* f_dt_b   = (const float*)d_in[8];
    const float* f_A_log  = (const float*)d_in[9];
    const float* f_D      = (const float*)d_in[10];
    const float* f_out_w  = (const float*)d_in[11];
    const float* b_in_w   = (const float*)d_in[12];
    const float* b_conv_w = (const float*)d_in[13];
    const float* b_conv_b = (const float*)d_in[14];
    const float* b_xproj_w= (const float*)d_in[15];
    const float* b_dt_w   = (const float*)d_in[16];
    const float* b_dt_b   = (const float*)d_in[17];
    const float* b_A_log  = (const float*)d_in[18];
    const float* b_D      = (const float*)d_in[19];
    const float* b_out_w  = (const float*)d_in[20];
    const float* mix_w    = (const float*)d_in[21];
    const float* mix_b    = (const float*)d_in[22];
    const float* ffn_w1   = (const float*)d_in[23];
    const float* ffn_b1   = (const float*)d_in[24];
    const float* ffn_w2   = (const float*)d_in[25];
    const float* ffn_b2   = (const float*)d_in[26];
    const float* ffn_norm_g = (const float*)d_in[27];
    const float* ffn_norm_b = (const float*)d_in[28];

    __half* xz_h  = (__half*)symv(g_xz_h);
    __half* xn_h  = (__half*)symv(g_xn_h);
    __half* xch_f = (__half*)symv(g_xch_f);
    float*  dbc_f = (float*) symv(g_dbc_f);
    __half* dbch_f= (__half*)symv(g_dbch_f);
    float*  dt_f  = (float*) symv(g_dt_f);
    __half* yh_f  = (__half*)symv(g_yh_f);
    __half* xch_b = (__half*)symv(g_xch_b);
    float*  dbc_b = (float*) symv(g_dbc_b);
    __half* dbch_b= (__half*)symv(g_dbch_b);
    float*  dt_bs = (float*) symv(g_dt_b);
    __half* yh_b  = (__half*)symv(g_yh_b);
    float*  h     = (float*) symv(g_h);
    __half* hn_h  = (__half*)symv(g_hn_h);
    __half* ff1_h = (__half*)symv(g_ff1_h);
    __half* wh    = (__half*)symv(g_wh);
    __half* owT   = (__half*)symv(g_owT);
    __half* wcomb = (__half*)symv(g_wcomb);
    float*  hp_f  = (float*) symv(g_hp_f);
    float*  pe_f  = (float*) symv(g_pe_f);
    float*  h0_f  = (float*) symv(g_h0_f);
    float*  hp_b  = (float*) symv(g_hp_b);
    float*  pe_b  = (float*) symv(g_pe_b);
    float*  h0_b  = (float*) symv(g_h0_b);
    float*  p0    = (float*) symv(g_p0);
    float*  p1    = (float*) symv(g_p1);
    float*  out   = (float*)d_out;

    static cudaStream_t s2 = nullptr;
    static cudaEvent_t evStart = nullptr, evCvt = nullptr, evB = nullptr,
                       evW = nullptr, evM2 = nullptr, evF = nullptr, evF2 = nullptr;
    if (!s2) {
        cudaStreamCreateWithFlags(&s2, cudaStreamNonBlocking);
        cudaEventCreateWithFlags(&evStart, cudaEventDisableTiming);
        cudaEventCreateWithFlags(&evCvt, cudaEventDisableTiming);
        cudaEventCreateWithFlags(&evB, cudaEventDisableTiming);
        cudaEventCreateWithFlags(&evW, cudaEventDisableTiming);
        cudaEventCreateWithFlags(&evM2, cudaEventDisableTiming);
        cudaEventCreateWithFlags(&evF, cudaEventDisableTiming);
        cudaEventCreateWithFlags(&evF2, cudaEventDisableTiming);
    }

    // fork s2 from main
    cudaEventRecord(evStart, 0);
    cudaStreamWaitEvent(s2, evStart, 0);

    // 0) weight fp16 conversion on s2 (hidden under LN1)
    CvtSegs<6> sa;
    sa.s[0] = f_in_w;    sa.d[0] = wh + OFF_FIN;  sa.n[0] = W_IN;
    sa.s[1] = b_in_w;    sa.d[1] = wh + OFF_BIN;  sa.n[1] = W_IN;
    sa.s[2] = f_xproj_w; sa.d[2] = wh + OFF_FXP;  sa.n[2] = W_XP;
    sa.s[3] = b_xproj_w; sa.d[3] = wh + OFF_BXP;  sa.n[3] = W_XP;
    sa.s[4] = f_dt_w;    sa.d[4] = wh + OFF_FDT;  sa.n[4] = W_DT;
    sa.s[5] = b_dt_w;    sa.d[5] = wh + OFF_BDT;  sa.n[5] = W_DT;
    cvt_weights<6><<<1024, 256, 0, s2>>>(sa);
    CvtSegs<3> sb;
    sb.s[0] = mix_w;     sb.d[0] = wh + OFF_MIX;  sb.n[0] = W_MIX;
    sb.s[1] = ffn_w1;    sb.d[1] = wh + OFF_FF1;  sb.n[1] = W_FF1;
    sb.s[2] = ffn_w2;    sb.d[2] = wh + OFF_FF2;  sb.n[2] = W_FF2;
    cvt_weights<3><<<1024, 256, 0, s2>>>(sb);
    cudaEventRecord(evCvt, s2);

    // 1) layernorm 1 -> fp16 (main, concurrent with cvt)
    layernorm_kernel<<<ROWS, 256>>>(x, norm_g, norm_b, xn_h);
    cudaStreamWaitEvent(0, evCvt, 0);

    // 2) merged fwd+bwd in_proj (launch #4 — profiled)
    launch_hgemm<0, false, false, true>(0, xn_h, nullptr, 0, DD, wh + OFF_FIN, DD,
                                        nullptr, xz_h, LDXZ, ROWS, LDXZ, DD, nullptr, nullptr, 0);
    cudaEventRecord(evB, 0);

    // s2: combined-weight prep
    transpose_w<<<dim3(DI / 32, DD / 32, 2), dim3(32, 32), 0, s2>>>(f_out_w, b_out_w, owT);
    launch_hgemm<0, false, false, true>(s2, wh + OFF_MIX, nullptr, 0, 2 * DD,
                                        owT, DD, nullptr, wcomb, 2 * DI,
                                        DD, DI, DD, nullptr, nullptr, 0);
    launch_hgemm<0, false, false, true>(s2, wh + OFF_MIX + DD, nullptr, 0, 2 * DD,
                                        owT + (size_t)DI * DD, DD, nullptr, wcomb + DI, 2 * DI,
                                        DD, DI, DD, nullptr, nullptr, 0);
    cudaEventRecord(evW, s2);

    // s2: wait for in_proj, run bwd branch
    cudaStreamWaitEvent(s2, evB, 0);
    run_mamba_tail<-1>(s2, xz_h + 2 * DI, xz_h + 3 * DI,
                       b_conv_w, b_conv_b, wh + OFF_BXP, wh + OFF_BDT, b_dt_b,
                       b_A_log, b_D,
                       xch_b, dbc_b, dbch_b, dt_bs, yh_b,
                       hp_b, pe_b, h0_b);
    // s2: mix partial-B = yh_b @ Wb'^T
    launch_hgemm<0, false, true, false>(s2, yh_b, nullptr, 0, DI, wcomb + DI, 2 * DI,
                                        p1, nullptr, DD, ROWS, DD, DI, nullptr, nullptr, 0);
    cudaEventRecord(evM2, s2);

    // main: fwd branch
    run_mamba_tail<1>(0, xz_h + 0, xz_h + DI,
                      f_conv_w, f_conv_b, wh + OFF_FXP, wh + OFF_FDT, f_dt_b,
                      f_A_log, f_D,
                      xch_f, dbc_f, dbch_f, dt_f, yh_f,
                      hp_f, pe_f, h0_f);

    // main: mix partial-A = yh_f @ Wf'^T
    cudaStreamWaitEvent(0, evW, 0);
    launch_hgemm<0, false, true, false>(0, yh_f, nullptr, 0, DI, wcomb, 2 * DI,
                                        p0, nullptr, DD, ROWS, DD, DI, nullptr, nullptr, 0);
    // reduce: h = p0 + p1 + mix_b + x
    cudaStreamWaitEvent(0, evM2, 0);
    reduce2_kernel<<<(ROWS * DD / 4 + 255) / 256, 256>>>(p0, p1, mix_b, x, h);

    // layernorm 2 -> fp16
    layernorm_kernel<<<ROWS, 256>>>(h, ffn_norm_g, ffn_norm_b, hn_h);

    // FFN1 + bias + gelu -> fp16
    launch_hgemm<1, false, false, true>(0, hn_h, nullptr, 0, DD, wh + OFF_FF1, DD,
                                        nullptr, ff1_h, 4 * DD, ROWS, 4 * DD, DD, ffn_b1, nullptr, 0);

    // FFN2 split-K across streams
    cudaEventRecord(evF, 0);
    cudaStreamWaitEvent(s2, evF, 0);
    launch_hgemm<0, false, true, false>(s2, ff1_h + 2 * DD, nullptr, 0, 4 * DD,
                                        wh + OFF_FF2 + 2 * DD, 4 * DD,
                                        p1, nullptr, DD, ROWS, DD, 2 * DD, nullptr, nullptr, 0);
    cudaEventRecord(evF2, s2);
    launch_hgemm<0, false, true, false>(0, ff1_h, nullptr, 0, 4 * DD,
                                        wh + OFF_FF2, 4 * DD,
                                        p0, nullptr, DD, ROWS, DD, 2 * DD, nullptr, nullptr, 0);
    cudaStreamWaitEvent(0, evF2, 0);
    // reduce: out = p0 + p1 + ffn_b2 + h
    reduce2_kernel<<<(ROWS * DD / 4 + 255) / 256, 256>>>(p0, p1, ffn_b2, h, out);
}

// round 16
// speedup vs baseline: 1.3118x; 1.1509x over previous
#include <cuda_runtime.h>
#include <cuda_fp16.h>
#include <cstdint>

// Problem constants
#define BB 2
#define LL 2048
#define DD 768
#define DI 1536
#define DS 16
#define DTR 48
#define KK 4
#define ROWS (BB*LL)            // 4096
#define DBC_W (DTR + 2*DS)      // 80
#define LDXZ (4*DI)             // 6144
#define NC 16                   // scan chunks
#define CL (LL/NC)              // 128 steps per chunk
#define DBLK (DI/16)            // 96 d-blocks of 16

// ---------------- scratch (device globals; allocation-free) ----------------
__device__ __align__(16) __half g_xz_h [(size_t)ROWS*LDXZ];
__device__ __align__(16) __half g_xn_h [ROWS*DD];
__device__ __align__(16) __half g_xch_f[(size_t)ROWS*DI];
__device__ __align__(16) float  g_dbc_f[(size_t)ROWS*DBC_W];
__device__ __align__(16) __half g_dbch_f[(size_t)ROWS*DBC_W];
__device__ __align__(16) float  g_dt_f [(size_t)ROWS*DI];
__device__ __align__(16) __half g_yh_f [(size_t)ROWS*DI];
__device__ __align__(16) __half g_xch_b[(size_t)ROWS*DI];
__device__ __align__(16) float  g_dbc_b[(size_t)ROWS*DBC_W];
__device__ __align__(16) __half g_dbch_b[(size_t)ROWS*DBC_W];
__device__ __align__(16) float  g_dt_b [(size_t)ROWS*DI];
__device__ __align__(16) __half g_yh_b [(size_t)ROWS*DI];
__device__ __align__(16) float  g_h    [ROWS*DD];
__device__ __align__(16) __half g_hn_h [ROWS*DD];
__device__ __align__(16) __half g_ff1_h[(size_t)ROWS*4*DD];
__device__ __align__(16) float  g_p0   [ROWS*DD];   // split-K partials
__device__ __align__(16) float  g_p1   [ROWS*DD];

// chunked-scan intermediates (per branch)
#define SCAN_ST (BB*DI*NC*DS)   // 786432
__device__ __align__(16) float g_hp_f[SCAN_ST];
__device__ __align__(16) float g_pe_f[SCAN_ST];
__device__ __align__(16) float g_h0_f[SCAN_ST];
__device__ __align__(16) float g_hp_b[SCAN_ST];
__device__ __align__(16) float g_pe_b[SCAN_ST];
__device__ __align__(16) float g_h0_b[SCAN_ST];

// fused out_proj+mix: transposed out weights + combined weights
__device__ __align__(16) __half g_owT  [2*(size_t)DI*DD];     // fowT | bowT
__device__ __align__(16) __half g_wcomb[(size_t)DD*2*DI];     // [768 x 3072]

// fp16 weight scratch
#define W_IN   (2*DI*DD)
#define W_XP   (DBC_W*DI)
#define W_DT   (DI*DTR)
#define W_MIX  (DD*2*DD)
#define W_FF1  (4*DD*DD)
#define W_FF2  (DD*4*DD)
#define OFF_FIN  0
#define OFF_BIN  (OFF_FIN + W_IN)
#define OFF_FXP  (OFF_BIN + W_IN)
#define OFF_BXP  (OFF_FXP + W_XP)
#define OFF_FDT  (OFF_BXP + W_XP)
#define OFF_BDT  (OFF_FDT + W_DT)
#define OFF_MIX  (OFF_BDT + W_DT)
#define OFF_FF1  (OFF_MIX + W_MIX)
#define OFF_FF2  (OFF_FF1 + W_FF1)
#define W_TOTAL  (OFF_FF2 + W_FF2)
__device__ __align__(16) __half g_wh[W_TOTAL];

// ---------------- helpers ----------------
__device__ __forceinline__ float siluf(float x) {
    return x / (1.0f + __expf(-x));
}
__device__ __forceinline__ float geluf(float x) {
    float x3 = x * x * x;
    return 0.5f * x * (1.0f + tanhf(0.7978845608028654f * (x + 0.044715f * x3)));
}
__device__ __forceinline__ float softplusf(float x) {
    if (x > 20.0f) return x;
    return log1pf(__expf(x));
}

__device__ __forceinline__ void cpa16(uint32_t dst, const void* src, bool v) {
    int sz = v ? 16 : 0;
    asm volatile("cp.async.cg.shared.global [%0], [%1], 16, %2;"
        :: "r"(dst), "l"(src), "r"(sz) : "memory");
}
#define CP_COMMIT() asm volatile("cp.async.commit_group;" ::: "memory")
#define CP_WAIT(n)  asm volatile("cp.async.wait_group %0;" :: "n"(n) : "memory")

__device__ __forceinline__ uint32_t smem_u32(const void* p) {
    uint32_t a;
    asm("{ .reg .u64 t; cvta.to.shared.u64 t, %1; cvt.u32.u64 %0, t; }" : "=r"(a) : "l"(p));
    return a;
}
__device__ __forceinline__ void mma_f16(float* d, const uint32_t* a, const uint32_t* b) {
    asm volatile("mma.sync.aligned.m16n8k16.row.col.f32.f16.f16.f32 "
                 "{%0,%1,%2,%3}, {%4,%5,%6,%7}, {%8,%9}, {%0,%1,%2,%3};"
                 : "+f"(d[0]), "+f"(d[1]), "+f"(d[2]), "+f"(d[3])
                 : "r"(a[0]), "r"(a[1]), "r"(a[2]), "r"(a[3]),
                   "r"(b[0]), "r"(b[1]));
}

// ---------------- one-shot weight conversion fp32 -> fp16 ----------------
template<int NS>
struct CvtSegs {
    const float* s[NS];
    __half* d[NS];
    int n[NS];
};
template<int NS>
__global__ void cvt_weights(CvtSegs<NS> sg) {
    int stride = gridDim.x * blockDim.x;
    int i0 = blockIdx.x * blockDim.x + threadIdx.x;
    #pragma unroll
    for (int k = 0; k < NS; k++) {
        const float4* s4 = (const float4*)sg.s[k];
        __half2* d2 = (__half2*)sg.d[k];
        int n4 = sg.n[k] >> 2;
        for (int i = i0; i < n4; i += stride) {
            float4 v = s4[i];
            d2[2*i]   = __floats2half2_rn(v.x, v.y);
            d2[2*i+1] = __floats2half2_rn(v.z, v.w);
        }
    }
}

// ---------------- out_w transpose: fp32 [768x1536] -> fp16 [1536x768] -----
__global__ void transpose_w(const float* __restrict__ s0, const float* __restrict__ s1,
                            __half* __restrict__ dst) {
    __shared__ __half tile[32][33];
    const float* src = blockIdx.z ? s1 : s0;
    __half* d = dst + (size_t)blockIdx.z * DI * DD;
    int kx = blockIdx.x * 32 + threadIdx.x;
    int jy = blockIdx.y * 32 + threadIdx.y;
    tile[threadIdx.y][threadIdx.x] = __float2half(src[(size_t)jy * DI + kx]);
    __syncthreads();
    int k = blockIdx.x * 32 + threadIdx.y;
    int j = blockIdx.y * 32 + threadIdx.x;
    d[(size_t)k * DD + j] = tile[threadIdx.x][threadIdx.y];
}

// ---------------- split-K reduce: C = p0 + p1 + bias + res ----------------
__global__ void reduce2_kernel(const float* __restrict__ p0,
                               const float* __restrict__ p1,
                               const float* __restrict__ bias,
                               const float* __restrict__ res,
                               float* __restrict__ C) {
    int i = blockIdx.x * blockDim.x + threadIdx.x;
    if (i * 4 >= ROWS * DD) return;
    float4 a = ((const float4*)p0)[i];
    float4 b = ((const float4*)p1)[i];
    float4 r = ((const float4*)res)[i];
    int col = (i * 4) % DD;
    a.x += b.x + bias[col + 0] + r.x;
    a.y += b.y + bias[col + 1] + r.y;
    a.z += b.z + bias[col + 2] + r.z;
    a.w += b.w + bias[col + 3] + r.w;
    ((float4*)C)[i] = a;
}

// ---------------- fused reduce + LayerNorm: h = p0+p1+bias+res; hn = LN(h) ----
__global__ void reduce_ln_kernel(const float* __restrict__ p0,
                                 const float* __restrict__ p1,
                                 const float* __restrict__ bias,
                                 const float* __restrict__ res,
                                 float* __restrict__ hout,
                                 const float* __restrict__ g,
                                 const float* __restrict__ bb,
                                 __half* __restrict__ out) {
    int row = blockIdx.x;
    size_t off = (size_t)row * DD;
    float v[3];
    float s = 0.f, s2 = 0.f;
    #pragma unroll
    for (int j = 0; j < 3; j++) {
        int i = threadIdx.x + j * 256;
        float t = p0[off + i] + p1[off + i] + bias[i] + res[off + i];
        v[j] = t;
        hout[off + i] = t;
        s += t; s2 += t * t;
    }
    __shared__ float shm[2][9];
    #pragma unroll
    for (int o = 16; o; o >>= 1) {
        s  += __shfl_xor_sync(0xffffffffu, s,  o);
        s2 += __shfl_xor_sync(0xffffffffu, s2, o);
    }
    int lane = threadIdx.x & 31, w = threadIdx.x >> 5;
    if (lane == 0) { shm[0][w] = s; shm[1][w] = s2; }
    __syncthreads();
    if (w == 0) {
        s  = (lane < 8) ? shm[0][lane] : 0.f;
        s2 = (lane < 8) ? shm[1][lane] : 0.f;
        #pragma unroll
        for (int o = 4; o; o >>= 1) {
            s  += __shfl_xor_sync(0xffffffffu, s,  o);
            s2 += __shfl_xor_sync(0xffffffffu, s2, o);
        }
        if (lane == 0) { shm[0][8] = s; shm[1][8] = s2; }
    }
    __syncthreads();
    float mu  = shm[0][8] * (1.0f / DD);
    float var = shm[1][8] * (1.0f / DD) - mu * mu;
    float inv = rsqrtf(var + 1e-5f);
    #pragma unroll
    for (int j = 0; j < 3; j++) {
        int i = threadIdx.x + j * 256;
        out[off + i] = __float2half((v[j] - mu) * inv * g[i] + bb[i]);
    }
}

// ================= fp16 mma.sync GEMM (fp32 accumulate) =================
#define GBM 128
#define GBN 128
#define GBK 64
#define KH 72
#define STAGE_B (GBM*KH*2)
#define SMEM_GEMM (4*STAGE_B)

template<int ACT, bool CAT, bool WF32, bool WH16>
__global__ __launch_bounds__(256, 2)
void hgemm(const __half* __restrict__ A, const __half* __restrict__ A2,
           int ksplit, int lda,
           const __half* __restrict__ W, int ldw,
           float* __restrict__ C, __half* __restrict__ Ch, int ldc,
           int M, int N, int Kd,
           const float* __restrict__ bias,
           const float* __restrict__ res, int ldres) {
    extern __shared__ __half smh[];
    __half* As = smh;
    __half* Bs = smh + 2 * GBM * KH;
    uint32_t sA = smem_u32(As);
    uint32_t sB = smem_u32(Bs);

    int tid = threadIdx.x;
    int lane = tid & 31, wid = tid >> 5;
    int bm = blockIdx.y * GBM, bn = blockIdx.x * GBN;
    int wm = (wid & 1) * 64, wn = (wid >> 1) * 32;
    int g = lane >> 2, l = lane & 3;

    float acc[4][4][4];
    #pragma unroll
    for (int f = 0; f < 4; f++)
        #pragma unroll
        for (int j = 0; j < 4; j++)
            #pragma unroll
            for (int c = 0; c < 4; c++) acc[f][j][c] = 0.f;

    auto load_stage = [&](int buf, int kt) {
        int k0 = kt * GBK;
        const __half* srcA = A;
        int kbase = k0;
        if (CAT && k0 >= ksplit) { srcA = A2; kbase = k0 - ksplit; }
        #pragma unroll
        for (int t = 0; t < 4; t++) {
            int c = tid + t * 256;
            int row = c >> 3, seg = c & 7;
            bool kv = (k0 + seg * 8) < Kd;
            int gm = bm + row;
            bool va = kv && (gm < M);
            cpa16(sA + buf * STAGE_B + row * (KH*2) + seg * 16,
                  srcA + (size_t)(va ? gm : 0) * lda + (va ? (kbase + seg * 8) : 0), va);
            int gn = bn + row;
            bool vb = kv && (gn < N);
            cpa16(sB + buf * STAGE_B + row * (KH*2) + seg * 16,
                  W + (size_t)(vb ? gn : 0) * ldw + (vb ? (k0 + seg * 8) : 0), vb);
        }
        CP_COMMIT();
    };

    const int NT = (Kd + GBK - 1) / GBK;
    load_stage(0, 0);

    for (int kt = 0; kt < NT; kt++) {
        int buf = kt & 1;
        if (kt + 1 < NT) {
            load_stage(buf ^ 1, kt + 1);
            CP_WAIT(1);
        } else {
            CP_WAIT(0);
        }
        __syncthreads();

        const uint32_t* as = (const uint32_t*)(As + buf * GBM * KH);
        const uint32_t* bs = (const uint32_t*)(Bs + buf * GBN * KH);
        #pragma unroll
        for (int s = 0; s < 4; s++) {
            int w0 = s * 8 + l;
            uint32_t af[4][4], bf[4][2];
            #pragma unroll
            for (int f = 0; f < 4; f++) {
                int r0 = wm + f * 16 + g;
                af[f][0] = as[r0 * 36 + w0];
                af[f][1] = as[(r0 + 8) * 36 + w0];
                af[f][2] = as[r0 * 36 + w0 + 4];
                af[f][3] = as[(r0 + 8) * 36 + w0 + 4];
            }
            #pragma unroll
            for (int j = 0; j < 4; j++) {
                int c0 = wn + j * 8 + g;
                bf[j][0] = bs[c0 * 36 + w0];
                bf[j][1] = bs[c0 * 36 + w0 + 4];
            }
            #pragma unroll
            for (int f = 0; f < 4; f++)
                #pragma unroll
                for (int j = 0; j < 4; j++)
                    mma_f16(acc[f][j], af[f], bf[j]);
        }
        __syncthreads();
    }

    // epilogue (vectorized: gn always even, pairs (gn, gn+1) contiguous)
    #pragma unroll
    for (int f = 0; f < 4; f++) {
        int gm0 = bm + wm + f * 16 + g;
        #pragma unroll
        for (int j = 0; j < 4; j++) {
            int gn = bn + wn + j * 8 + 2 * l;
            if (gn + 1 >= N) continue;
            float b0 = bias ? bias[gn] : 0.f;
            float b1 = bias ? bias[gn + 1] : 0.f;
            #pragma unroll
            for (int half_i = 0; half_i < 2; half_i++) {
                int gm = gm0 + half_i * 8;
                if (gm >= M) continue;
                float v0 = acc[f][j][half_i * 2 + 0] + b0;
                float v1 = acc[f][j][half_i * 2 + 1] + b1;
                if (ACT == 1) { v0 = geluf(v0); v1 = geluf(v1); }
                else if (ACT == 2) { v0 = softplusf(v0); v1 = softplusf(v1); }
                if (res) {
                    float2 rv = *(const float2*)(res + (size_t)gm * ldres + gn);
                    v0 += rv.x;
                    v1 += rv.y;
                }
                if (WF32) {
                    float2 ov = {v0, v1};
                    *(float2*)(C + (size_t)gm * ldc + gn) = ov;
                }
                if (WH16) {
                    *(__half2*)(Ch + (size_t)gm * ldc + gn) = __floats2half2_rn(v0, v1);
                }
            }
        }
    }
}

// ---------------- LayerNorm (fp32 in, fp16 out) ----------
__global__ void layernorm_kernel(const float* __restrict__ x,
                                 const float* __restrict__ g,
                                 const float* __restrict__ b,
                                 __half* __restrict__ out) {
    int row = blockIdx.x;
    const float* xr = x + (size_t)row * DD;
    float s = 0.f, s2 = 0.f;
    for (int i = threadIdx.x; i < DD; i += blockDim.x) {
        float v = xr[i];
        s += v; s2 += v * v;
    }
    __shared__ float shm[2][33];
    #pragma unroll
    for (int off = 16; off; off >>= 1) {
        s  += __shfl_xor_sync(0xffffffffu, s,  off);
        s2 += __shfl_xor_sync(0xffffffffu, s2, off);
    }
    int lane = threadIdx.x & 31, w = threadIdx.x >> 5;
    if (lane == 0) { shm[0][w] = s; shm[1][w] = s2; }
    __syncthreads();
    int nw = blockDim.x >> 5;
    if (w == 0) {
        s  = (lane < nw) ? shm[0][lane] : 0.f;
        s2 = (lane < nw) ? shm[1][lane] : 0.f;
        #pragma unroll
        for (int off = 16; off; off >>= 1) {
            s  += __shfl_xor_sync(0xffffffffu, s,  off);
            s2 += __shfl_xor_sync(0xffffffffu, s2, off);
        }
        if (lane == 0) { shm[0][32] = s; shm[1][32] = s2; }
    }
    __syncthreads();
    float mu  = shm[0][32] * (1.0f / DD);
    float var = shm[1][32] * (1.0f / DD) - mu * mu;
    float inv = rsqrtf(var + 1e-5f);
    __half* orow = out + (size_t)row * DD;
    for (int i = threadIdx.x; i < DD; i += blockDim.x)
        orow[i] = __float2half((xr[i] - mu) * inv * g[i] + b[i]);
}

// ---------------- causal conv (K=4) + bias + silu -> fp16 only ----------
template<int DIR>
__global__ void conv_silu_kernel(const __half* __restrict__ xzx,
                                 const float* __restrict__ cw,
                                 const float* __restrict__ cb,
                                 __half* __restrict__ out_h) {
    int idx = blockIdx.x * blockDim.x + threadIdx.x;
    if (idx >= ROWS * DI) return;
    int d = idx % DI;
    int t = (idx / DI) % LL;
    int b = idx / (DI * LL);
    float acc = cb[d];
    #pragma unroll
    for (int k = 0; k < KK; k++) {
        int tt = (DIR > 0) ? (t - (KK - 1) + k) : (t + (KK - 1) - k);
        if (tt >= 0 && tt < LL)
            acc += __half2float(xzx[((size_t)(b * LL + tt)) * LDXZ + d]) * cw[d * KK + k];
    }
    out_h[idx] = __float2half(siluf(acc));
}

// ---------------- chunked parallel scan (d-coalesced block mapping) -------
template<int DIR>
__global__ void scan_part1(const float* __restrict__ dt,
                           const __half* __restrict__ xch,
                           const float* __restrict__ dbc,
                           const float* __restrict__ A_log,
                           float* __restrict__ hp, float* __restrict__ pe) {
    int bid = blockIdx.x;
    int dblk = bid % DBLK;
    int c = (bid / DBLK) % NC;
    int b = bid / (DBLK * NC);
    int s = threadIdx.x & 15;
    int d = dblk * 16 + (threadIdx.x >> 4);
    float Aval = -__expf(A_log[d * DS + s]);
    float h = 0.f, p = 1.f;
    size_t base = (size_t)b * LL;
    int u0 = c * CL;
    for (int i = 0; i < CL; i++) {
        int u = u0 + i;
        int t = (DIR > 0) ? u : (LL - 1 - u);
        size_t row = base + t;
        float dtv = dt[row * DI + d];
        float xv  = __half2float(xch[row * DI + d]);
        float Bv  = dbc[row * DBC_W + DTR + s];
        float e = __expf(dtv * Aval);
        h = e * h + dtv * xv * Bv;
        p *= e;
    }
    size_t o = (((size_t)(b * DI + d)) * NC + c) * DS + s;
    hp[o] = h;
    pe[o] = p;
}

__global__ void scan_part2(const float* __restrict__ hp,
                           const float* __restrict__ pe,
                           float* __restrict__ h0) {
    int i = blockIdx.x * blockDim.x + threadIdx.x;
    if (i >= BB * DI * DS) return;
    int s = i & (DS - 1);
    int gd = i >> 4;
    float H = 0.f;
    #pragma unroll
    for (int c = 0; c < NC; c++) {
        size_t o = ((size_t)gd * NC + c) * DS + s;
        h0[o] = H;
        H = hp[o] + H * pe[o];
    }
}

template<int DIR>
__global__ void scan_part3(const float* __restrict__ dt,
                           const __half* __restrict__ xch,
                           const float* __restrict__ dbc,
                           const __half* __restrict__ zp,
                           const float* __restrict__ A_log,
                           const float* __restrict__ Dp,
                           const float* __restrict__ h0,
                           __half* __restrict__ y) {
    int bid = blockIdx.x;
    int dblk = bid % DBLK;
    int c = (bid / DBLK) % NC;
    int b = bid / (DBLK * NC);
    int s = threadIdx.x & 15;
    int d = dblk * 16 + (threadIdx.x >> 4);
    float Aval = -__expf(A_log[d * DS + s]);
    float Dv = Dp[d];
    float h = h0[(((size_t)(b * DI + d)) * NC + c) * DS + s];
    size_t base = (size_t)b * LL;
    int u0 = c * CL;
    for (int i = 0; i < CL; i++) {
        int u = u0 + i;
        int t = (DIR > 0) ? u : (LL - 1 - u);
        size_t row = base + t;
        float dtv = dt[row * DI + d];
        float xv  = __half2float(xch[row * DI + d]);
        float Bv  = dbc[row * DBC_W + DTR + s];
        float Cv  = dbc[row * DBC_W + DTR + DS + s];
        float e = __expf(dtv * Aval);
        h = e * h + dtv * xv * Bv;
        float part = h * Cv;
        #pragma unroll
        for (int off = 8; off; off >>= 1)
            part += __shfl_xor_sync(0xffffffffu, part, off);
        if (s == 0) {
            float zv = __half2float(zp[row * LDXZ + d]);
            y[row * DI + d] = __float2half((part + xv * Dv) * siluf(zv));
        }
    }
}

// ---------------- host side ----------------
static void* symv(const void* s) {
    void* p = nullptr;
    cudaGetSymbolAddress(&p, s);
    return p;
}

template<int ACT, bool CAT, bool WF32, bool WH16>
static void launch_hgemm(cudaStream_t st,
                         const __half* A, const __half* A2, int ksplit, int lda,
                         const __half* W, int ldw,
                         float* C, __half* Ch, int ldc,
                         int M, int N, int Kd,
                         const float* bias, const float* res, int ldres) {
    static bool attr_set = false;
    if (!attr_set) {
        cudaFuncSetAttribute(hgemm<ACT, CAT, WF32, WH16>,
                             cudaFuncAttributeMaxDynamicSharedMemorySize, SMEM_GEMM);
        attr_set = true;
    }
    dim3 grid((N + GBN - 1) / GBN, (M + GBM - 1) / GBM);
    hgemm<ACT, CAT, WF32, WH16><<<grid, 256, SMEM_GEMM, st>>>(
        A, A2, ksplit, lda, W, ldw, C, Ch, ldc, M, N, Kd, bias, res, ldres);
}

template<int DIR>
static void run_mamba_tail(cudaStream_t st,
                           const __half* xzx, const __half* zp,
                           const float* conv_w, const float* conv_b,
                           const __half* xproj_wh, const __half* dt_wh, const float* dt_b,
                           const float* A_log, const float* Dp,
                           __half* xch, float* dbc, __half* dbch,
                           float* dt, __half* yh,
                           float* hp, float* pe, float* h0) {
    conv_silu_kernel<DIR><<<(ROWS * DI + 255) / 256, 256, 0, st>>>(xzx, conv_w, conv_b, xch);
    launch_hgemm<0, false, true, true>(st, xch, nullptr, 0, DI, xproj_wh, DI,
                                       dbc, dbch, DBC_W, ROWS, DBC_W, DI, nullptr, nullptr, 0);
    launch_hgemm<2, false, true, false>(st, dbch, nullptr, 0, DBC_W, dt_wh, DTR,
                                        dt, nullptr, DI, ROWS, DI, DTR, dt_b, nullptr, 0);
    scan_part1<DIR><<<BB * NC * DBLK, 256, 0, st>>>(dt, xch, dbc, A_log, hp, pe);
    scan_part2<<<(BB * DI * DS + 255) / 256, 256, 0, st>>>(hp, pe, h0);
    scan_part3<DIR><<<BB * NC * DBLK, 256, 0, st>>>(dt, xch, dbc, zp, A_log, Dp, h0, yh);
}

extern "C" void kernel_launch(void* const* d_in, const int* in_sizes, int n_in,
                              void* d_out, int out_size) {
    const float* x        = (const float*)d_in[0];
    const float* norm_g   = (const float*)d_in[1];
    const float* norm_b   = (const float*)d_in[2];
    const float* f_in_w   = (const float*)d_in[3];
    const float* f_conv_w = (const float*)d_in[4];
    const float* f_conv_b = (const float*)d_in[5];
    const float* f_xproj_w= (const float*)d_in[6];
    const float* f_dt_w   = (const float*)d_in[7];
    const float* f_dt_b   = (const float*)d_in[8];
    const float* f_A_log  = (const float*)d_in[9];
    const float* f_D      = (const float*)d_in[10];
    const float* f_out_w  = (const float*)d_in[11];
    const float* b_in_w   = (const float*)d_in[12];
    const float* b_conv_w = (const float*)d_in[13];
    const float* b_conv_b = (const float*)d_in[14];
    const float* b_xproj_w= (const float*)d_in[15];
    const float* b_dt_w   = (const float*)d_in[16];
    const float* b_dt_b   = (const float*)d_in[17];
    const float* b_A_log  = (const float*)d_in[18];
    const float* b_D      = (const float*)d_in[19];
    const float* b_out_w  = (const float*)d_in[20];
    const float* mix_w    = (const float*)d_in[21];
    const float* mix_b    = (const float*)d_in[22];
    const float* ffn_w1   = (const float*)d_in[23];
    const float* ffn_b1   = (const float*)d_in[24];
    const float* ffn_w2   = (const float*)d_in[25];
    const float* ffn_b2   = (const float*)d_in[26];
    const float* ffn_norm_g = (const float*)d_in[27];
    const float* ffn_norm_b = (const float*)d_in[28];

    __half* xz_h  = (__half*)symv(g_xz_h);
    __half* xn_h  = (__half*)symv(g_xn_h);
    __half* xch_f = (__half*)symv(g_xch_f);
    float*  dbc_f = (float*) symv(g_dbc_f);
    __half* dbch_f= (__half*)symv(g_dbch_f);
    float*  dt_f  = (float*) symv(g_dt_f);
    __half* yh_f  = (__half*)symv(g_yh_f);
    __half* xch_b = (__half*)symv(g_xch_b);
    float*  dbc_b = (float*) symv(g_dbc_b);
    __half* dbch_b= (__half*)symv(g_dbch_b);
    float*  dt_bs = (float*) symv(g_dt_b);
    __half* yh_b  = (__half*)symv(g_yh_b);
    float*  h     = (float*) symv(g_h);
    __half* hn_h  = (__half*)symv(g_hn_h);
    __half* ff1_h = (__half*)symv(g_ff1_h);
    __half* wh    = (__half*)symv(g_wh);
    __half* owT   = (__half*)symv(g_owT);
    __half* wcomb = (__half*)symv(g_wcomb);
    float*  hp_f  = (float*) symv(g_hp_f);
    float*  pe_f  = (float*) symv(g_pe_f);
    float*  h0_f  = (float*) symv(g_h0_f);
    float*  hp_b  = (float*) symv(g_hp_b);
    float*  pe_b  = (float*) symv(g_pe_b);
    float*  h0_b  = (float*) symv(g_h0_b);
    float*  p0    = (float*) symv(g_p0);
    float*  p1    = (float*) symv(g_p1);
    float*  out   = (float*)d_out;

    static cudaStream_t s2 = nullptr;
    static cudaEvent_t evStart = nullptr, evCvt = nullptr, evB = nullptr,
                       evW = nullptr, evM2 = nullptr, evL = nullptr, evF2 = nullptr;
    if (!s2) {
        cudaStreamCreateWithFlags(&s2, cudaStreamNonBlocking);
        cudaEventCreateWithFlags(&evStart, cudaEventDisableTiming);
        cudaEventCreateWithFlags(&evCvt, cudaEventDisableTiming);
        cudaEventCreateWithFlags(&evB, cudaEventDisableTiming);
        cudaEventCreateWithFlags(&evW, cudaEventDisableTiming);
        cudaEventCreateWithFlags(&evM2, cudaEventDisableTiming);
        cudaEventCreateWithFlags(&evL, cudaEventDisableTiming);
        cudaEventCreateWithFlags(&evF2, cudaEventDisableTiming);
    }

    // fork s2 from main
    cudaEventRecord(evStart, 0);
    cudaStreamWaitEvent(s2, evStart, 0);

    // 0) weight fp16 conversion on s2 (hidden under LN1)
    CvtSegs<6> sa;
    sa.s[0] = f_in_w;    sa.d[0] = wh + OFF_FIN;  sa.n[0] = W_IN;
    sa.s[1] = b_in_w;    sa.d[1] = wh + OFF_BIN;  sa.n[1] = W_IN;
    sa.s[2] = f_xproj_w; sa.d[2] = wh + OFF_FXP;  sa.n[2] = W_XP;
    sa.s[3] = b_xproj_w; sa.d[3] = wh + OFF_BXP;  sa.n[3] = W_XP;
    sa.s[4] = f_dt_w;    sa.d[4] = wh + OFF_FDT;  sa.n[4] = W_DT;
    sa.s[5] = b_dt_w;    sa.d[5] = wh + OFF_BDT;  sa.n[5] = W_DT;
    cvt_weights<6><<<1024, 256, 0, s2>>>(sa);
    CvtSegs<3> sb;
    sb.s[0] = mix_w;     sb.d[0] = wh + OFF_MIX;  sb.n[0] = W_MIX;
    sb.s[1] = ffn_w1;    sb.d[1] = wh + OFF_FF1;  sb.n[1] = W_FF1;
    sb.s[2] = ffn_w2;    sb.d[2] = wh + OFF_FF2;  sb.n[2] = W_FF2;
    cvt_weights<3><<<1024, 256, 0, s2>>>(sb);
    cudaEventRecord(evCvt, s2);

    // 1) layernorm 1 -> fp16 (main, concurrent with cvt)
    layernorm_kernel<<<ROWS, 256>>>(x, norm_g, norm_b, xn_h);
    cudaStreamWaitEvent(0, evCvt, 0);

    // 2) merged fwd+bwd in_proj (launch #4 — profiled)
    launch_hgemm<0, false, false, true>(0, xn_h, nullptr, 0, DD, wh + OFF_FIN, DD,
                                        nullptr, xz_h, LDXZ, ROWS, LDXZ, DD, nullptr, nullptr, 0);
    cudaEventRecord(evB, 0);

    // s2: combined-weight prep
    transpose_w<<<dim3(DI / 32, DD / 32, 2), dim3(32, 32), 0, s2>>>(f_out_w, b_out_w, owT);
    launch_hgemm<0, false, false, true>(s2, wh + OFF_MIX, nullptr, 0, 2 * DD,
                                        owT, DD, nullptr, wcomb, 2 * DI,
                                        DD, DI, DD, nullptr, nullptr, 0);
    launch_hgemm<0, false, false, true>(s2, wh + OFF_MIX + DD, nullptr, 0, 2 * DD,
                                        owT + (size_t)DI * DD, DD, nullptr, wcomb + DI, 2 * DI,
                                        DD, DI, DD, nullptr, nullptr, 0);
    cudaEventRecord(evW, s2);

    // s2: wait for in_proj, run bwd branch
    cudaStreamWaitEvent(s2, evB, 0);
    run_mamba_tail<-1>(s2, xz_h + 2 * DI, xz_h + 3 * DI,
                       b_conv_w, b_conv_b, wh + OFF_BXP, wh + OFF_BDT, b_dt_b,
                       b_A_log, b_D,
                       xch_b, dbc_b, dbch_b, dt_bs, yh_b,
                       hp_b, pe_b, h0_b);
    // s2: mix partial-B = yh_b @ Wb'^T
    launch_hgemm<0, false, true, false>(s2, yh_b, nullptr, 0, DI, wcomb + DI, 2 * DI,
                                        p1, nullptr, DD, ROWS, DD, DI, nullptr, nullptr, 0);
    cudaEventRecord(evM2, s2);

    // main: fwd branch
    run_mamba_tail<1>(0, xz_h + 0, xz_h + DI,
                      f_conv_w, f_conv_b, wh + OFF_FXP, wh + OFF_FDT, f_dt_b,
                      f_A_log, f_D,
                      xch_f, dbc_f, dbch_f, dt_f, yh_f,
                      hp_f, pe_f, h0_f);

    // main: mix partial-A = yh_f @ Wf'^T
    cudaStreamWaitEvent(0, evW, 0);
    launch_hgemm<0, false, true, false>(0, yh_f, nullptr, 0, DI, wcomb, 2 * DI,
                                        p0, nullptr, DD, ROWS, DD, DI, nullptr, nullptr, 0);
    // fused reduce + layernorm2: h = p0+p1+mix_b+x; hn = LN(h)
    cudaStreamWaitEvent(0, evM2, 0);
    reduce_ln_kernel<<<ROWS, 256>>>(p0, p1, mix_b, x, h, ffn_norm_g, ffn_norm_b, hn_h);

    // FFN split across streams:
    //  main: ff1 cols [0,1536) -> FFN2 partial K [0,1536)
    //  s2:   ff1 cols [1536,3072) -> FFN2 partial K [1536,3072)
    cudaEventRecord(evL, 0);
    cudaStreamWaitEvent(s2, evL, 0);
    // s2 half
    launch_hgemm<1, false, false, true>(s2, hn_h, nullptr, 0, DD,
                                        wh + OFF_FF1 + (size_t)2 * DD * DD, DD,
                                        nullptr, ff1_h + 2 * DD, 4 * DD,
                                        ROWS, 2 * DD, DD, ffn_b1 + 2 * DD, nullptr, 0);
    launch_hgemm<0, false, true, false>(s2, ff1_h + 2 * DD, nullptr, 0, 4 * DD,
                                        wh + OFF_FF2 + 2 * DD, 4 * DD,
                                        p1, nullptr, DD, ROWS, DD, 2 * DD, nullptr, nullptr, 0);
    cudaEventRecord(evF2, s2);
    // main half
    launch_hgemm<1, false, false, true>(0, hn_h, nullptr, 0, DD,
                                        wh + OFF_FF1, DD,
                                        nullptr, ff1_h, 4 * DD,
                                        ROWS, 2 * DD, DD, ffn_b1, nullptr, 0);
    launch_hgemm<0, false, true, false>(0, ff1_h, nullptr, 0, 4 * DD,
                                        wh + OFF_FF2, 4 * DD,
                                        p0, nullptr, DD, ROWS, DD, 2 * DD, nullptr, nullptr, 0);
    cudaStreamWaitEvent(0, evF2, 0);
    // reduce: out = p0 + p1 + ffn_b2 + h
    reduce2_kernel<<<(ROWS * DD / 4 + 255) / 256, 256>>>(p0, p1, ffn_b2, h, out);
}